// round 12
// baseline (speedup 1.0000x reference)
#include <cuda_runtime.h>
#include <cuda_fp16.h>
#include <cstdint>
#include <cstddef>

#define TPB   128
#define NKEY  127
#define NH    4
#define DK    64
#define DOUT  256
#define STRH  80    // fp16 row stride in halves (160B = 40 words)
#define STGF  68    // fp32 staging row stride in floats
#define MAXT  4

static constexpr int OFFB_STG  = 0;
static constexpr int OFFB_KV16 = OFFB_STG  + 128 * STGF * 4;   // 34816
static constexpr int OFFB_WK16 = OFFB_KV16 + 128 * STRH * 2;   // +20480
static constexpr int OFFB_QBA  = OFFB_WK16 + 256 * STRH * 2;   // +40960
static constexpr int OFFB_QT   = OFFB_QBA + MAXT * DOUT * 4;
static constexpr int OFFB_WS   = OFFB_QT + MAXT * DK * 4;
static constexpr int OFFB_W    = OFFB_WS + DK * 4;             // [4][128] head-major
static constexpr int OFFB_WV   = OFFB_W + NH * 128 * 4;        // [256]
static constexpr int OFFB_BS   = OFFB_WV + DOUT * 4;
static constexpr int SMEM_BYTES = OFFB_BS + 16;                // ~104.8 KB

__device__ __forceinline__ float tanh_fast(float x) {
    float y;
    asm("tanh.approx.f32 %0, %1;" : "=f"(y) : "f"(x));
    return y;
}
__device__ __forceinline__ uint32_t f2h2(float a, float b) {
    __half2 h = __floats2half2_rn(a, b);
    return *(uint32_t*)&h;
}

// m16n8k16 fp16 MMA, row(A) x col(B), fp32 accumulate (arch-neutral PTX)
__device__ __forceinline__ void mma16(float& d0, float& d1, float& d2,
                                      float& d3, uint32_t a0, uint32_t a1,
                                      uint32_t a2, uint32_t a3,
                                      uint32_t b0, uint32_t b1) {
    asm volatile(
        "mma.sync.aligned.m16n8k16.row.col.f32.f16.f16.f32 "
        "{%0,%1,%2,%3}, {%4,%5,%6,%7}, {%8,%9}, {%0,%1,%2,%3};"
        : "+f"(d0), "+f"(d1), "+f"(d2), "+f"(d3)
        : "r"(a0), "r"(a1), "r"(a2), "r"(a3), "r"(b0), "r"(b1));
}

#define CP_ASYNC16(sdst, gsrc)                                                \
    asm volatile("cp.async.cg.shared.global [%0], [%1], 16;"                  \
                 :: "r"(sdst), "l"(gsrc))
#define CP_COMMIT() asm volatile("cp.async.commit_group;")
#define CP_WAIT0()  asm volatile("cp.async.wait_group 0;")

__device__ __forceinline__ void prefetch_kv(const float* __restrict__ gsrc,
                                            float* stg) {
    #pragma unroll 1
    for (int j = threadIdx.x; j < NKEY * 16; j += TPB) {
        int row = j >> 4;
        int c4  = j & 15;
        unsigned sa =
            (unsigned)__cvta_generic_to_shared(stg + row * STGF + c4 * 4);
        CP_ASYNC16(sa, gsrc + j * 4);
    }
}

__global__ void __launch_bounds__(TPB, 2)
raamh_kernel(const float* __restrict__ q_x, const float* __restrict__ kv_x,
             const float* __restrict__ Wk,  const float* __restrict__ Wq,
             const float* __restrict__ Wv,  const float* __restrict__ bias,
             const float* __restrict__ Ws,  const float* __restrict__ bs,
             float* __restrict__ out, int BT)
{
    extern __shared__ char smem[];
    float*  s_stg  = (float*) (smem + OFFB_STG);
    __half* s_kvh  = (__half*)(smem + OFFB_KV16);
    __half* s_wkh  = (__half*)(smem + OFFB_WK16);
    float*  s_qba  = (float*) (smem + OFFB_QBA);
    float*  s_qt   = (float*) (smem + OFFB_QT);
    float*  s_ws   = (float*) (smem + OFFB_WS);
    float*  s_w    = (float*) (smem + OFFB_W);    // [head][128]
    float*  s_wv   = (float*) (smem + OFFB_WV);
    float*  s_bs   = (float*) (smem + OFFB_BS);

    const int tid  = threadIdx.x;
    const int lane = tid & 31;
    const int wrp  = tid >> 5;       // warp's head
    const int g    = lane >> 2;
    const int tg   = lane & 3;

    const int bt0  = blockIdx.x;
    const int grid = gridDim.x;
    int ntiles = (BT - bt0 + grid - 1) / grid;
    if (ntiles > MAXT) ntiles = MAXT;
    if (ntiles < 1) return;

    prefetch_kv(kv_x + (size_t)bt0 * (NKEY * DK), s_stg);
    CP_COMMIT();

    // ---- one-time staging: Wk -> fp16, ws, bs, qt, zero kv row 127 ----
    {
        #pragma unroll 1
        for (int j = tid; j < DOUT * 16; j += TPB) {
            int row = j >> 4, c4 = (j & 15) * 4;
            float4 v = __ldg((const float4*)(Wk + row * DK + c4));
            uint2 hh = make_uint2(f2h2(v.x, v.y), f2h2(v.z, v.w));
            *(uint2*)(s_wkh + row * STRH + c4) = hh;
        }
        if (tid < DK) s_ws[tid] = Ws[tid];
        if (tid == 0) s_bs[0] = bs[0];
        if (tid < 16) {
            uint2 z = make_uint2(0u, 0u);
            *(uint2*)(s_kvh + 127 * STRH + tid * 4) = z;
        }
        for (int idx = tid; idx < ntiles * DK; idx += TPB) {
            int t = idx >> 6, k = idx & 63;
            s_qt[t * DK + k] = q_x[(size_t)(bt0 + t * grid) * DK + k];
        }
    }
    __syncthreads();

    // ---- prologue: qb for every tile; thread covers o = tid, tid+128 ----
    #pragma unroll 1
    for (int rep = 0; rep < 2; ++rep) {
        const int o = tid + rep * 128;
        float4 wq[16];
        const float4* wq4 = (const float4*)(Wq + o * DK);
        #pragma unroll
        for (int i = 0; i < 16; i++) wq[i] = __ldg(wq4 + i);
        const float bb = __ldg(bias + (o & (DK - 1)));
        #pragma unroll 1
        for (int t = 0; t < ntiles; ++t) {
            const float* qq = s_qt + t * DK;
            float a0 = 0.f, a1 = 0.f, a2 = 0.f, a3 = 0.f;
            #pragma unroll
            for (int i = 0; i < 16; i++) {
                a0 = fmaf(qq[4 * i + 0], wq[i].x, a0);
                a1 = fmaf(qq[4 * i + 1], wq[i].y, a1);
                a2 = fmaf(qq[4 * i + 2], wq[i].z, a2);
                a3 = fmaf(qq[4 * i + 3], wq[i].w, a3);
            }
            s_qba[t * DOUT + o] = (a0 + a1) + (a2 + a3) + bb;
        }
    }

    int ti = 0;
    for (int bt = bt0; bt < BT; bt += grid, ++ti) {
        CP_WAIT0();
        __syncthreads();           // staging ready; prior tile fully consumed

        // ---- convert staging -> fp16 kv ----
        if (tid < NKEY) {
            const float* src = s_stg + tid * STGF;
            __half* dst = s_kvh + tid * STRH;
            #pragma unroll
            for (int u = 0; u < 16; ++u) {
                float4 v = *(const float4*)(src + u * 4);
                uint2 hh = make_uint2(f2h2(v.x, v.y), f2h2(v.z, v.w));
                *(uint2*)(dst + u * 4) = hh;
            }
        }
        __syncthreads();           // kv16 ready; staging free

        int bt_next = bt + grid;
        if (bt_next < BT)
            prefetch_kv(kv_x + (size_t)bt_next * (NKEY * DK), s_stg);
        CP_COMMIT();

        const float* qbt = s_qba + ti * DOUT;
        const float  bsv = s_bs[0];
        const int head = wrp;
        const __half* wkp = s_wkh + (head * 64) * STRH;

        // ---- scores for head `wrp`: 16 per lane, kept in registers ----
        float sc[16];              // [nh*4 + mb*2 + p], n = nh*32+mb*16+p*8+g
        #pragma unroll 1
        for (int nh = 0; nh < 4; ++nh) {
            const __half* kvp = s_kvh + (nh * 32) * STRH;

            float acc[2][8][4];
            #pragma unroll
            for (int mb = 0; mb < 2; ++mb)
                #pragma unroll
                for (int nb = 0; nb < 8; ++nb)
                    #pragma unroll
                    for (int c = 0; c < 4; ++c) acc[mb][nb][c] = 0.f;

            #pragma unroll
            for (int kc = 0; kc < 4; ++kc) {
                const int ho = kc * 16 + 4 * tg;   // permuted k slots
                uint2 u[2], v[2];
                #pragma unroll
                for (int mb = 0; mb < 2; ++mb) {
                    const __half* ar = kvp + (mb * 16 + g) * STRH + ho;
                    u[mb] = *(const uint2*)ar;
                    v[mb] = *(const uint2*)(ar + 8 * STRH);
                }
                #pragma unroll
                for (int nb = 0; nb < 8; ++nb) {
                    uint2 w = *(const uint2*)(wkp + (nb * 8 + g) * STRH + ho);
                    #pragma unroll
                    for (int mb = 0; mb < 2; ++mb)
                        mma16(acc[mb][nb][0], acc[mb][nb][1],
                              acc[mb][nb][2], acc[mb][nb][3],
                              u[mb].x, v[mb].x, u[mb].y, v[mb].y,
                              w.x, w.y);
                }
            }

            float part[2][2];
            part[0][0] = part[0][1] = part[1][0] = part[1][1] = 0.f;
            #pragma unroll
            for (int nb = 0; nb < 8; ++nb) {
                #pragma unroll
                for (int cc = 0; cc < 2; ++cc) {
                    const int k = nb * 8 + tg * 2 + cc;
                    const float wsk = s_ws[k];
                    const float qbo = qbt[head * 64 + k];
                    #pragma unroll
                    for (int mb = 0; mb < 2; ++mb) {
                        part[mb][0] = fmaf(
                            wsk, tanh_fast(acc[mb][nb][cc] + qbo),
                            part[mb][0]);
                        part[mb][1] = fmaf(
                            wsk, tanh_fast(acc[mb][nb][2 + cc] + qbo),
                            part[mb][1]);
                    }
                }
            }
            #pragma unroll
            for (int m = 1; m <= 2; m <<= 1) {
                #pragma unroll
                for (int mb = 0; mb < 2; ++mb) {
                    part[mb][0] += __shfl_xor_sync(0xffffffffu, part[mb][0], m);
                    part[mb][1] += __shfl_xor_sync(0xffffffffu, part[mb][1], m);
                }
            }
            sc[nh * 4 + 0] = part[0][0] + bsv;
            sc[nh * 4 + 1] = part[0][1] + bsv;
            sc[nh * 4 + 2] = part[1][0] + bsv;
            sc[nh * 4 + 3] = part[1][1] + bsv;
        }

        // mask n = 127 (nh=3, mb=1, p=1, g=7)
        if (g == 7) sc[15] = -1e30f;

        // ---- warp-local softmax over 128 scores ----
        float mx = -1e30f;
        #pragma unroll
        for (int i = 0; i < 16; ++i) mx = fmaxf(mx, sc[i]);
        #pragma unroll
        for (int off = 4; off <= 16; off <<= 1)
            mx = fmaxf(mx, __shfl_xor_sync(0xffffffffu, mx, off));
        float sum = 0.f;
        #pragma unroll
        for (int i = 0; i < 16; ++i) {
            sc[i] = __expf(sc[i] - mx);
            sum += sc[i];
        }
        #pragma unroll
        for (int off = 4; off <= 16; off <<= 1)
            sum += __shfl_xor_sync(0xffffffffu, sum, off);
        const float inv = 1.f / sum;
        if (tg == 0) {
            #pragma unroll
            for (int i = 0; i < 16; ++i) {
                const int n = (i >> 2) * 32 + ((i >> 1) & 1) * 16 +
                              (i & 1) * 8 + g;
                s_w[head * 128 + n] = sc[i] * inv;
            }
        }
        __syncwarp();

        // ---- warp-local weighted kv sum for this head ----
        {
            const int c2 = lane * 2;
            const float* wr = s_w + head * 128;
            float ax0 = 0.f, ay0 = 0.f, ax1 = 0.f, ay1 = 0.f;
            #pragma unroll 2
            for (int n = 0; n < 126; n += 2) {
                float w0 = wr[n], w1 = wr[n + 1];
                float2 f0 = __half22float2(
                    *(const __half2*)(s_kvh + n * STRH + c2));
                float2 f1 = __half22float2(
                    *(const __half2*)(s_kvh + (n + 1) * STRH + c2));
                ax0 = fmaf(w0, f0.x, ax0);
                ay0 = fmaf(w0, f0.y, ay0);
                ax1 = fmaf(w1, f1.x, ax1);
                ay1 = fmaf(w1, f1.y, ay1);
            }
            {
                float w0 = wr[126];
                float2 f0 = __half22float2(
                    *(const __half2*)(s_kvh + 126 * STRH + c2));
                ax0 = fmaf(w0, f0.x, ax0);
                ay0 = fmaf(w0, f0.y, ay0);
            }
            s_wv[head * 64 + c2]     = ax0 + ax1;
            s_wv[head * 64 + c2 + 1] = ay0 + ay1;
        }
        __syncthreads();           // all wv ready

        // ---- output projection: thread covers o = tid, tid+128 ----
        #pragma unroll 1
        for (int rep = 0; rep < 2; ++rep) {
            const int o = tid + rep * 128;
            const float* wvh = s_wv + (o >> 6) * 64;
            const float4* wv4 = (const float4*)(Wv + o * DK);
            float a0 = 0.f, a1 = 0.f, a2 = 0.f, a3 = 0.f;
            #pragma unroll
            for (int i = 0; i < 16; i++) {
                float4 w = __ldg(wv4 + i);
                a0 = fmaf(wvh[4 * i + 0], w.x, a0);
                a1 = fmaf(wvh[4 * i + 1], w.y, a1);
                a2 = fmaf(wvh[4 * i + 2], w.z, a2);
                a3 = fmaf(wvh[4 * i + 3], w.w, a3);
            }
            out[(size_t)bt * DOUT + o] = (a0 + a1) + (a2 + a3);
        }
    }
}

extern "C" void kernel_launch(void* const* d_in, const int* in_sizes, int n_in,
                              void* d_out, int out_size) {
    (void)n_in; (void)out_size;
    const float* q_x  = (const float*)d_in[0];
    const float* kv_x = (const float*)d_in[1];
    const float* Wk   = (const float*)d_in[2];
    const float* Wq   = (const float*)d_in[3];
    const float* Wv   = (const float*)d_in[4];
    const float* bias = (const float*)d_in[5];
    const float* Ws   = (const float*)d_in[6];
    const float* bs   = (const float*)d_in[7];
    float* out = (float*)d_out;

    const int BT = in_sizes[0] / DK;
    int grid = 2 * 152;
    if (grid > BT) grid = BT;
    while ((BT + grid - 1) / grid > MAXT) grid += 2 * 152;

    cudaFuncSetAttribute(raamh_kernel,
                         cudaFuncAttributeMaxDynamicSharedMemorySize,
                         SMEM_BYTES);
    raamh_kernel<<<grid, TPB, SMEM_BYTES>>>(q_x, kv_x, Wk, Wq, Wv,
                                            bias, Ws, bs, out, BT);
}